// round 3
// baseline (speedup 1.0000x reference)
#include <cuda_runtime.h>
#include <math.h>

#define TMAX 2048
#define S 193          // stride of 192x192 bordered workspace (odd -> conflict-free columns)
#define S2 65          // stride of persistent 64x64 blocks
#define NTHREADS 256
#define LOG2PI 1.8378770664093453f

// ---------------- device scratch (no allocations allowed) ----------------
__device__ float gSaa[64 * 64];
__device__ float gSabT[64 * 64];
__device__ float gSbb[64 * 64];
__device__ float gMuT[TMAX * 64];
__device__ float gIvdT[TMAX * 64];
__device__ float gFvar[64 * 64];
__device__ float gFmu[64];
__device__ float gFscore;

// ---------------- precompute transition blocks ----------------
// trans_var = trans_cho^T @ trans_cho (128x128).
// gSaa[r][c]  = tv[r][c]        (r,c < 64)
// gSabT[r][c] = tv[c][64+r]     (= Sab^T)
// gSbb[r][c]  = tv[64+r][64+c]
__global__ void __launch_bounds__(256) prek_kernel(const float* __restrict__ tcho) {
    extern __shared__ float s[];   // 128*128 floats
    int tid = threadIdx.x;
    for (int i = tid; i < 128 * 128; i += 256) s[i] = tcho[i];
    __syncthreads();
    int which = blockIdx.x;
    int r0 = (tid >> 4) << 2, c0 = (tid & 15) << 2;
    int ra = (which == 0) ? r0 : (64 + r0);
    int cb = (which == 2) ? (64 + c0) : c0;
    float acc[4][4];
#pragma unroll
    for (int q = 0; q < 4; q++)
#pragma unroll
        for (int w = 0; w < 4; w++) acc[q][w] = 0.f;
    for (int k = 0; k < 128; ++k) {
        const float* row = s + (k << 7);
        float a[4], b[4];
#pragma unroll
        for (int q = 0; q < 4; q++) a[q] = row[ra + q];
#pragma unroll
        for (int w = 0; w < 4; w++) b[w] = row[cb + w];
#pragma unroll
        for (int q = 0; q < 4; q++)
#pragma unroll
            for (int w = 0; w < 4; w++) acc[q][w] += a[q] * b[w];
    }
    float* dst = (which == 0) ? gSaa : ((which == 1) ? gSabT : gSbb);
#pragma unroll
    for (int q = 0; q < 4; q++)
#pragma unroll
        for (int w = 0; w < 4; w++) dst[(r0 + q) * 64 + c0 + w] = acc[q][w];
}

// ---------------- gather token embeddings ----------------
__global__ void gather_kernel(const int* __restrict__ sent,
                              const float* __restrict__ memb,
                              const float* __restrict__ cemb, int n) {
    int t = blockIdx.x;
    if (t >= n) return;
    int c = threadIdx.x;   // 64 threads
    int tok = sent[t];
    gMuT[t * 64 + c] = memb[tok * 64 + c];
    float ch = cemb[tok * 64 + c];
    gIvdT[t * 64 + c] = ch * ch;
}

// ---------------- sequential scan: bordered 192x192 factorization per step ----------------
__global__ void __launch_bounds__(NTHREADS, 1) scan_kernel(const float* __restrict__ tmu,
                                                           const int* __restrict__ slenp) {
    extern __shared__ float sm[];
    float* M    = sm;                       // 192*193
    float* sSaa = sm + 192 * S;             // 64*65 each
    float* sSab = sSaa + 64 * S2;
    float* sSbb = sSab + 64 * S2;
    float* v    = sSbb + 64 * S2;           // 192
    float* sMu  = v + 192;                  // 64
    float* sMuA = sMu + 64;
    float* sMuB = sMuA + 64;
    float* sIm  = sMuB + 64;
    float* sIvd = sIm + 64;
    float* sInv = sIvd + 64;                // 128
    float* sRed = sInv + 128;               // 8
    float* sSc  = sRed + 8;                 // 1

    int tid = threadIdx.x;
    int slen = slenp[0];
    if (slen > TMAX) slen = TMAX;
    if (slen < 0) slen = 0;

    for (int idx = tid; idx < 64 * 64; idx += NTHREADS) {
        int r = idx >> 6, c = idx & 63;
        sSaa[r * S2 + c] = gSaa[idx];
        sSab[r * S2 + c] = gSabT[idx];
        sSbb[r * S2 + c] = gSbb[idx];
    }
    if (tid < 64) {
        sMuA[tid] = tmu[tid];
        sMuB[tid] = tmu[64 + tid];
        sIm[tid] = 0.f;     // init iteration: mu1 = 0
        sIvd[tid] = 1.f;    // init iteration: var1 = I
    }
    if (tid == 0) sSc[0] = 0.f;
    __syncthreads();

    float pim = 0.f, pivd = 0.f;
    for (int t = -1; t < slen; ++t) {
        // prefetch token t+1 into registers (consumed at end of this iteration)
        if (t + 1 < slen) {
            if (tid < 64) pim = gMuT[(t + 1) * 64 + tid];
            else if (tid < 128) pivd = gIvdT[(t + 1) * 64 + (tid - 64)];
        }
        int jstart = (t < 0) ? 64 : 0;

        // ---- phase A: capture previous state (var_t -> block(0,0), mu_t -> sMu) ----
        if (t >= 0) {
            for (int idx = tid; idx < 64 * 64; idx += NTHREADS) {
                int i = idx >> 6, k = idx & 63;
                if (k <= i) {
                    float val = M[(128 + i) * S + 128 + k];
                    if (k == i) val += sIvd[i];
                    M[i * S + k] = val;       // vs = V + D (lower)
                }
            }
            if (tid < 64) sMu[tid] = v[128 + tid];
        }
        __syncthreads();

        // ---- phase B: rebuild remaining blocks and RHS ----
        for (int idx = tid; idx < 64 * 64; idx += NTHREADS) {
            int i = idx >> 6, k = idx & 63;
            M[(64 + i) * S + k] = (i == k) ? sIvd[i] : 0.f;                    // block(1,0) = D
            if (k <= i) M[(64 + i) * S + 64 + k] =
                sSaa[i * S2 + k] + ((i == k) ? sIvd[i] : 0.f);                 // block(1,1) = Saa + D
            M[(128 + i) * S + 64 + k] = sSab[i * S2 + k];                      // block(2,1) = Sab^T
            if (k <= i) M[(128 + i) * S + 128 + k] = sSbb[i * S2 + k];         // block(2,2) = Sbb
        }
        if (tid < 64) {
            v[tid]       = sMu[tid]  - sIm[tid];   // mu_prev - im
            v[64 + tid]  = sMuA[tid] - sIm[tid];   // mu_a - im
            v[128 + tid] = sMuB[tid];              // mu_b
        }
        __syncthreads();

        // ---- factorization: eliminate columns jstart..127 (panelled, B=16) ----
        for (int p = (jstart >> 4); p < 8; ++p) {
            int c0 = p << 4;
            int rlim = (c0 < 64) ? 128 : 192;   // rows >=128 untouched while j<64 (block(2,0)=0)

            // panel factorization: 1 barrier per column
            for (int jj = 0; jj < 16; ++jj) {
                int j = c0 + jj;
                float piv = M[j * S + j];
                float rp = __frcp_rn(piv);
                if (tid == 0) sInv[j] = rp;
                int k = j + 1 + (tid & 15);
                if (k < c0 + 16) {
                    float mk = M[k * S + j] * rp;
                    for (int i = k + (tid >> 4); i < rlim; i += 16)
                        M[i * S + k] -= M[i * S + j] * mk;
                }
                int iv = j + 1 + tid;
                if (iv < rlim) v[iv] -= M[iv * S + j] * (v[j] * rp);
                __syncthreads();
            }

            // rank-16 trailing update, register-tiled 4x4, lower-triangle tiles only
            int t0 = c0 + 16;
            int n = rlim - t0;                    // always a multiple of 16
            int ntile = n >> 2;
            int ntri = (ntile * (ntile + 1)) >> 1;
            for (int m = tid; m < ntri; m += NTHREADS) {
                int ti = (int)((sqrtf(8.f * (float)m + 1.f) - 1.f) * 0.5f);
                while ((ti + 1) * (ti + 2) / 2 <= m) ++ti;
                while (ti * (ti + 1) / 2 > m) --ti;
                int tk = m - ((ti * (ti + 1)) >> 1);
                int i0 = t0 + (ti << 2), k0 = t0 + (tk << 2);
                float acc[4][4];
#pragma unroll
                for (int q = 0; q < 4; q++)
#pragma unroll
                    for (int w = 0; w < 4; w++) acc[q][w] = M[(i0 + q) * S + k0 + w];
#pragma unroll
                for (int jj = 0; jj < 16; ++jj) {
                    int j = c0 + jj;
                    float ivj = sInv[j];
                    float a[4], b[4];
#pragma unroll
                    for (int q = 0; q < 4; q++) a[q] = M[(i0 + q) * S + j];
#pragma unroll
                    for (int w = 0; w < 4; w++) b[w] = M[(k0 + w) * S + j] * ivj;
#pragma unroll
                    for (int q = 0; q < 4; q++)
#pragma unroll
                        for (int w = 0; w < 4; w++) acc[q][w] -= a[q] * b[w];
                }
#pragma unroll
                for (int q = 0; q < 4; q++)
#pragma unroll
                    for (int w = 0; w < 4; w++) M[(i0 + q) * S + k0 + w] = acc[q][w];
            }
            __syncthreads();
        }

        // ---- score reduction: sum over eliminated pivots of v^2/piv + log(piv) ----
        float my = 0.f;
        if (tid >= jstart && tid < 128) {
            float ivj = sInv[tid];
            float z = v[tid];
            my = z * z * ivj - logf(ivj);   // log(piv) = -log(inv)
        }
        for (int o = 16; o > 0; o >>= 1) my += __shfl_down_sync(0xffffffffu, my, o);
        if ((tid & 31) == 0 && tid < 128) sRed[tid >> 5] = my;

        // stage next token's im/ivd (last read of current ones was phase B)
        if (t + 1 < slen) {
            if (tid < 64) sIm[tid] = pim;
            else if (tid < 128) sIvd[tid - 64] = pivd;
        }
        __syncthreads();
        if (tid == 0) {
            float tot = sRed[0] + sRed[1] + sRed[2] + sRed[3];
            float cnt = (t < 0) ? 64.f : 128.f;
            sSc[0] += -0.5f * (cnt * LOG2PI + tot);
        }
        __syncthreads();
    }

    // ---- export final state ----
    for (int idx = tid; idx < 64 * 64; idx += NTHREADS) {
        int i = idx >> 6, k = idx & 63;
        gFvar[idx] = (k <= i) ? M[(128 + i) * S + 128 + k] : 0.f;
    }
    if (tid < 64) gFmu[tid] = v[128 + tid];
    if (tid == 0) gFscore = sSc[0];
}

// ---------------- decode: 50 independent 64x64 Cholesky scores ----------------
__global__ void __launch_bounds__(64) decode_kernel(const float* __restrict__ omu,
                                                    const float* __restrict__ ocho,
                                                    float* __restrict__ out, int nlab) {
    __shared__ float A[64 * S2];
    __shared__ float z[64];
    __shared__ float red[2];
    int l = blockIdx.x;
    if (l >= nlab) return;
    int i = threadIdx.x;   // 64 threads, thread i owns row i
    for (int k = 0; k <= i; ++k) A[i * S2 + k] = gFvar[i * 64 + k];
    float oc = ocho[l * 64 + i];
    A[i * S2 + i] += oc * oc;
    z[i] = gFmu[i] - omu[l * 64 + i];
    __syncthreads();
    float acc = 0.f;
    for (int j = 0; j < 64; ++j) {
        float piv = A[j * S2 + j];
        float rp = __frcp_rn(piv);
        if (i == j) acc = logf(piv) + z[j] * z[j] * rp;
        if (i > j) {
            float mij = A[i * S2 + j];
            z[i] -= mij * (z[j] * rp);
            float mjr = mij * rp;
            for (int k = j + 1; k <= i; ++k) A[i * S2 + k] -= mjr * A[k * S2 + j];
        }
        __syncthreads();
    }
    for (int o = 16; o > 0; o >>= 1) acc += __shfl_down_sync(0xffffffffu, acc, o);
    if ((i & 31) == 0) red[i >> 5] = acc;
    __syncthreads();
    if (i == 0) out[l] = gFscore - 0.5f * (64.f * LOG2PI + red[0] + red[1]);
}

// ---------------- launch ----------------
static const int SCAN_SMEM_BYTES = (192 * S + 3 * 64 * S2 + 192 + 5 * 64 + 128 + 8 + 4) * 4;

extern "C" void kernel_launch(void* const* d_in, const int* in_sizes, int n_in,
                              void* d_out, int out_size) {
    const int*   sent = (const int*)d_in[0];
    const int*   slen = (const int*)d_in[1];
    const float* memb = (const float*)d_in[2];
    const float* cemb = (const float*)d_in[3];
    const float* tmu  = (const float*)d_in[4];
    const float* tcho = (const float*)d_in[5];
    const float* omu  = (const float*)d_in[6];
    const float* ocho = (const float*)d_in[7];
    float* out = (float*)d_out;

    int n = in_sizes[0];
    if (n > TMAX) n = TMAX;
    int nlab = out_size;
    if (nlab <= 0) nlab = in_sizes[6] / 64;

    cudaFuncSetAttribute(prek_kernel, cudaFuncAttributeMaxDynamicSharedMemorySize, 128 * 128 * 4);
    cudaFuncSetAttribute(scan_kernel, cudaFuncAttributeMaxDynamicSharedMemorySize, SCAN_SMEM_BYTES);

    prek_kernel<<<3, 256, 128 * 128 * 4>>>(tcho);
    gather_kernel<<<n, 64>>>(sent, memb, cemb, n);
    scan_kernel<<<1, NTHREADS, SCAN_SMEM_BYTES>>>(tmu, slen);
    decode_kernel<<<nlab, 64>>>(omu, ocho, out, nlab);
}